// round 2
// baseline (speedup 1.0000x reference)
#include <cuda_runtime.h>

#define BATCH   32
#define CDIM    192
#define PDIM    3136
#define TP      8                    // patches per block -> 392 blocks
#define SSTR    260                  // smem c-stride (2*SSTR % 32 == 8 -> bv loads conflict-free)
#define THREADS 1024
#define NROW    (CDIM/8)             // 24 tile-rows
#define NTASK   156                  // sum over rows r of ceil((r+1)/2)
#define SMEM_BYTES (CDIM * SSTR * 4) // 199680 B

__global__ __launch_bounds__(THREADS, 1)
void padim_kernel(const float* __restrict__ emb,
                  const float* __restrict__ means_in,
                  const float* __restrict__ cov_in,
                  float* __restrict__ out_means,
                  float* __restrict__ out_cov)
{
    extern __shared__ float sm[];   // sm[c*SSTR + b*TP + ii]
    const int i0  = blockIdx.x * TP;
    const int tid = threadIdx.x;

    // ---- Stage embeddings slice [C][B][TP] into smem (full 32B sectors from gmem).
    for (int p = tid; p < BATCH * CDIM; p += THREADS) {
        const int b = p / CDIM;
        const int c = p - b * CDIM;
        const float4* g = reinterpret_cast<const float4*>(
            emb + (size_t)b * CDIM * PDIM + (size_t)c * PDIM + i0);
        float4 v0 = g[0];
        float4 v1 = g[1];
        float* s = sm + c * SSTR + b * TP;
        s[0] = v0.x; s[1] = v0.y; s[2] = v0.z; s[3] = v0.w;
        s[4] = v1.x; s[5] = v1.y; s[6] = v1.z; s[7] = v1.w;
    }
    __syncthreads();

    // ---- Means: out_means[i, c] = means_in[i, c] + sum_b emb[b, c, i]
    for (int p = tid; p < CDIM * TP; p += THREADS) {
        const int c  = p >> 3;
        const int ii = p & 7;
        const float* s = sm + c * SSTR + ii;
        float ssum = 0.f;
        #pragma unroll
        for (int b = 0; b < BATCH; b++) ssum += s[b * TP];
        const size_t idx = (size_t)(i0 + ii) * CDIM + c;
        out_means[idx] = means_in[idx] + ssum;
    }

    // ---- Covariance. Warp-task = tile-row tc, td-pair (td0, td0+1), 8 patches.
    // Lane (ii = lane>>2 : patch, q = lane&3 : v-slot). Each lane accumulates
    // acc[tile][u=0..7][j=0..1] for v = 2q + j of its two tiles. 32 acc regs.
    const int wid  = tid >> 5;
    const int lane = tid & 31;
    const int ii   = lane >> 2;
    const int q    = lane & 3;

    for (int t = wid; t < NTASK; t += THREADS / 32) {
        // decode task -> (tc, td0). pairs in row r = r/2 + 1. t uniform per warp.
        int r = 0, cum = 0;
        while (cum + (r >> 1) + 1 <= t) { cum += (r >> 1) + 1; r++; }
        const int tc  = r;
        const int td0 = (t - cum) * 2;
        const int td1 = td0 + 1;
        const bool has2 = (td1 <= tc);

        float acc0[8][2], acc1[8][2];
        #pragma unroll
        for (int u = 0; u < 8; u++) {
            acc0[u][0] = 0.f; acc0[u][1] = 0.f;
            acc1[u][0] = 0.f; acc1[u][1] = 0.f;
        }

        const float* sa  = sm + (tc * 8) * SSTR + ii;
        const float* sb0 = sm + (td0 * 8 + 2 * q) * SSTR + ii;
        const float* sb1 = sb0 + 8 * SSTR;   // rows stay < CDIM even when !has2

        #pragma unroll 1
        for (int b = 0; b < BATCH; b++) {
            const int bo = b * TP;
            float av[8];
            #pragma unroll
            for (int u = 0; u < 8; u++) av[u] = sa[u * SSTR + bo];
            const float b00 = sb0[bo];
            const float b01 = sb0[SSTR + bo];
            const float b10 = sb1[bo];
            const float b11 = sb1[SSTR + bo];
            #pragma unroll
            for (int u = 0; u < 8; u++) {
                acc0[u][0] = fmaf(av[u], b00, acc0[u][0]);
                acc0[u][1] = fmaf(av[u], b01, acc0[u][1]);
                acc1[u][0] = fmaf(av[u], b10, acc1[u][0]);
                acc1[u][1] = fmaf(av[u], b11, acc1[u][1]);
            }
        }

        const size_t cov_base = (size_t)(i0 + ii) * CDIM * CDIM;

        // Main tiles: row u, cols td*8 + 2q + {0,1}  (float2 RMW, q-groups -> 32B sectors)
        #pragma unroll
        for (int u = 0; u < 8; u++) {
            const size_t off0 = cov_base + (size_t)(tc * 8 + u) * CDIM + td0 * 8 + 2 * q;
            float2 c0 = *reinterpret_cast<const float2*>(cov_in + off0);
            c0.x += acc0[u][0]; c0.y += acc0[u][1];
            *reinterpret_cast<float2*>(out_cov + off0) = c0;
            if (has2) {
                const size_t off1 = off0 + 8;
                float2 c1 = *reinterpret_cast<const float2*>(cov_in + off1);
                c1.x += acc1[u][0]; c1.y += acc1[u][1];
                *reinterpret_cast<float2*>(out_cov + off1) = c1;
            }
        }

        // Mirror tiles: row td*8 + 2q + j holds acc[0..7][j] (full 8 floats per lane)
        if (td0 != tc) {
            #pragma unroll
            for (int j = 0; j < 2; j++) {
                const size_t off = cov_base + (size_t)(td0 * 8 + 2 * q + j) * CDIM + tc * 8;
                const float4* gin = reinterpret_cast<const float4*>(cov_in + off);
                float4* gout      = reinterpret_cast<float4*>(out_cov + off);
                float4 m0 = gin[0];
                float4 m1 = gin[1];
                m0.x += acc0[0][j]; m0.y += acc0[1][j]; m0.z += acc0[2][j]; m0.w += acc0[3][j];
                m1.x += acc0[4][j]; m1.y += acc0[5][j]; m1.z += acc0[6][j]; m1.w += acc0[7][j];
                gout[0] = m0;
                gout[1] = m1;
            }
        }
        if (has2 && td1 != tc) {
            #pragma unroll
            for (int j = 0; j < 2; j++) {
                const size_t off = cov_base + (size_t)(td1 * 8 + 2 * q + j) * CDIM + tc * 8;
                const float4* gin = reinterpret_cast<const float4*>(cov_in + off);
                float4* gout      = reinterpret_cast<float4*>(out_cov + off);
                float4 m0 = gin[0];
                float4 m1 = gin[1];
                m0.x += acc1[0][j]; m0.y += acc1[1][j]; m0.z += acc1[2][j]; m0.w += acc1[3][j];
                m1.x += acc1[4][j]; m1.y += acc1[5][j]; m1.z += acc1[6][j]; m1.w += acc1[7][j];
                gout[0] = m0;
                gout[1] = m1;
            }
        }
    }
}

extern "C" void kernel_launch(void* const* d_in, const int* in_sizes, int n_in,
                              void* d_out, int out_size)
{
    const float* emb   = (const float*)d_in[0];  // [B, C, P]
    const float* means = (const float*)d_in[1];  // [P, C]
    const float* cov   = (const float*)d_in[2];  // [P, C, C]
    float* out       = (float*)d_out;
    float* out_means = out;                              // [P, C]
    float* out_cov   = out + (size_t)PDIM * CDIM;        // [P, C, C]

    cudaFuncSetAttribute(padim_kernel,
                         cudaFuncAttributeMaxDynamicSharedMemorySize, SMEM_BYTES);
    padim_kernel<<<PDIM / TP, THREADS, SMEM_BYTES>>>(emb, means, cov,
                                                     out_means, out_cov);
}